// round 2
// baseline (speedup 1.0000x reference)
#include <cuda_runtime.h>

#define BB 64
#define NN 256
#define EE 2048
#define DD 128
#define HH 4
#define NEG_SLOPE 0.2f

// Precomputed folded weight vectors (per branch, per head) + constant term.
__device__ float g_ws[2][HH][DD];   // a_src folded through W
__device__ float g_wd[2][HH][DD];   // a_dst folded through W
__device__ float g_u [2][HH][DD];   // mlp_w slice folded through W^T
__device__ float g_const;

__global__ void precompute_kernel(const float* __restrict__ W1,
                                  const float* __restrict__ as1,
                                  const float* __restrict__ ad1,
                                  const float* __restrict__ W2,
                                  const float* __restrict__ as2,
                                  const float* __restrict__ ad2,
                                  const float* __restrict__ mlp_w,
                                  const float* __restrict__ mlp_b,
                                  const float* __restrict__ b1,
                                  const float* __restrict__ b2) {
    int br = blockIdx.x >> 2;       // 0..1
    int h  = blockIdx.x & 3;        // 0..3
    int k  = threadIdx.x;           // 0..127
    const float* W   = br ? W2  : W1;
    const float* as_ = br ? as2 : as1;
    const float* ad_ = br ? ad2 : ad1;
    const float* mw  = mlp_w + br * DD;

    float aws = 0.f, awd = 0.f, au = 0.f;
    #pragma unroll 8
    for (int d = 0; d < DD; ++d) {
        float wv = W[(h * DD + d) * DD + k];   // coalesced across k
        aws += wv * as_[h * DD + d];
        awd += wv * ad_[h * DD + d];
        au  += wv * mw[d];
    }
    g_ws[br][h][k] = aws;
    g_wd[br][h][k] = awd;
    g_u [br][h][k] = au;

    if (blockIdx.x == 0 && k == 0) {
        float c = mlp_b[0];
        for (int d = 0; d < DD; ++d) c += mlp_w[d] * b1[d] + mlp_w[DD + d] * b2[d];
        g_const = c;
    }
}

__global__ __launch_bounds__(256)
void gat_main(const int* __restrict__ nbr1, const int* __restrict__ nbr2,
              const int* __restrict__ adj1, const int* __restrict__ adj2,
              const float* __restrict__ emb, float* __restrict__ out) {
    __shared__ float sws[HH][DD], swd[HH][DD], su[HH][DD];
    __shared__ float s_adst[HH];
    __shared__ float wM[8][HH], wS[8][HH], wT[8][HH];

    const int b    = blockIdx.x;
    const int tid  = threadIdx.x;
    const int warp = tid >> 5;
    const int lane = tid & 31;
    const float NEGINF = __int_as_float(0xff800000);

    float total = 0.f;   // meaningful on thread 0 only

    for (int br = 0; br < 2; ++br) {
        const int* nbr  = (br ? nbr2 : nbr1) + b * NN;
        const int* srcA = (br ? adj2 : adj1) + (long)b * 2 * EE;
        const int* dstA = srcA + EE;

        // Stage folded weights into smem
        const float* gws = &g_ws[br][0][0];
        const float* gwd = &g_wd[br][0][0];
        const float* gu  = &g_u [br][0][0];
        for (int i = tid; i < HH * DD; i += 256) {
            (&sws[0][0])[i] = gws[i];
            (&swd[0][0])[i] = gwd[i];
            (&su [0][0])[i] = gu [i];
        }
        __syncthreads();

        // adst for the center node (warp 0)
        if (warp == 0) {
            const float* x0 = emb + (long)nbr[0] * DD;
            float a0 = 0, a1 = 0, a2 = 0, a3 = 0;
            #pragma unroll
            for (int c = 0; c < 4; ++c) {
                int d = lane + 32 * c;
                float xv = x0[d];
                a0 += xv * swd[0][d]; a1 += xv * swd[1][d];
                a2 += xv * swd[2][d]; a3 += xv * swd[3][d];
            }
            #pragma unroll
            for (int o = 16; o; o >>= 1) {
                a0 += __shfl_xor_sync(0xffffffffu, a0, o);
                a1 += __shfl_xor_sync(0xffffffffu, a1, o);
                a2 += __shfl_xor_sync(0xffffffffu, a2, o);
                a3 += __shfl_xor_sync(0xffffffffu, a3, o);
            }
            if (lane == 0) { s_adst[0] = a0; s_adst[1] = a1; s_adst[2] = a2; s_adst[3] = a3; }
        }
        __syncthreads();
        const float adst0 = s_adst[0], adst1 = s_adst[1],
                    adst2 = s_adst[2], adst3 = s_adst[3];

        // Per-warp online softmax state (replicated on all lanes)
        float m[HH], s[HH], t[HH];
        #pragma unroll
        for (int h = 0; h < HH; ++h) { m[h] = NEGINF; s[h] = 0.f; t[h] = 0.f; }

        // Warp-cooperative processing of one source node j (dst == 0 edge)
        auto process = [&](int j) {
            const float* x = emb + (long)nbr[j] * DD;
            float a0 = 0, a1 = 0, a2 = 0, a3 = 0;
            float p0 = 0, p1 = 0, p2 = 0, p3 = 0;
            #pragma unroll
            for (int c = 0; c < 4; ++c) {
                int d = lane + 32 * c;
                float xv = x[d];
                a0 += xv * sws[0][d]; a1 += xv * sws[1][d];
                a2 += xv * sws[2][d]; a3 += xv * sws[3][d];
                p0 += xv * su [0][d]; p1 += xv * su [1][d];
                p2 += xv * su [2][d]; p3 += xv * su [3][d];
            }
            #pragma unroll
            for (int o = 16; o; o >>= 1) {
                a0 += __shfl_xor_sync(0xffffffffu, a0, o);
                a1 += __shfl_xor_sync(0xffffffffu, a1, o);
                a2 += __shfl_xor_sync(0xffffffffu, a2, o);
                a3 += __shfl_xor_sync(0xffffffffu, a3, o);
                p0 += __shfl_xor_sync(0xffffffffu, p0, o);
                p1 += __shfl_xor_sync(0xffffffffu, p1, o);
                p2 += __shfl_xor_sync(0xffffffffu, p2, o);
                p3 += __shfl_xor_sync(0xffffffffu, p3, o);
            }
            float ev[HH] = { a0 + adst0, a1 + adst1, a2 + adst2, a3 + adst3 };
            float pv[HH] = { p0, p1, p2, p3 };
            #pragma unroll
            for (int h = 0; h < HH; ++h) {
                float e = ev[h] > 0.f ? ev[h] : NEG_SLOPE * ev[h];   // leaky_relu
                float nm = fmaxf(m[h], e);
                float fo = expf(m[h] - nm);
                float fn = expf(e - nm);
                s[h] = s[h] * fo + fn;
                t[h] = t[h] * fo + pv[h] * fn;
                m[h] = nm;
            }
        };

        // Self-loop for the center node (reference appends loop edges)
        if (warp == 0) process(0);

        // Scan this warp's slice of edges for dst == 0
        const int base0 = warp * (EE / 8);
        for (int base = base0; base < base0 + EE / 8; base += 32) {
            int dv = dstA[base + lane];
            int sv = srcA[base + lane];
            unsigned ballot = __ballot_sync(0xffffffffu, dv == 0);
            while (ballot) {
                int i = __ffs(ballot) - 1;
                ballot &= ballot - 1;
                int j = __shfl_sync(0xffffffffu, sv, i);
                process(j);
            }
        }

        if (lane == 0) {
            #pragma unroll
            for (int h = 0; h < HH; ++h) {
                wM[warp][h] = m[h]; wS[warp][h] = s[h]; wT[warp][h] = t[h];
            }
        }
        __syncthreads();

        // Deterministic merge of 8 warp partials (thread 0)
        if (tid == 0) {
            #pragma unroll
            for (int h = 0; h < HH; ++h) {
                float M = NEGINF, S = 0.f, T = 0.f;
                for (int w = 0; w < 8; ++w) {
                    float mw_ = wM[w][h], sw_ = wS[w][h], tw_ = wT[w][h];
                    if (sw_ == 0.f) continue;
                    float nm = fmaxf(M, mw_);
                    float fo = expf(M - nm);
                    float fn = expf(mw_ - nm);
                    S = S * fo + sw_ * fn;
                    T = T * fo + tw_ * fn;
                    M = nm;
                }
                total += (T / S) * (1.f / HH);
            }
        }
        __syncthreads();   // protect smem before next branch reload
    }

    if (tid == 0) out[b] = total + g_const;
}

extern "C" void kernel_launch(void* const* d_in, const int* in_sizes, int n_in,
                              void* d_out, int out_size) {
    const int*   nbr1 = (const int*)  d_in[0];
    const int*   nbr2 = (const int*)  d_in[1];
    const int*   adj1 = (const int*)  d_in[2];
    const int*   adj2 = (const int*)  d_in[3];
    const float* emb  = (const float*)d_in[4];
    const float* W1   = (const float*)d_in[5];
    const float* as1  = (const float*)d_in[6];
    const float* ad1  = (const float*)d_in[7];
    const float* b1   = (const float*)d_in[8];
    const float* W2   = (const float*)d_in[9];
    const float* as2  = (const float*)d_in[10];
    const float* ad2  = (const float*)d_in[11];
    const float* b2   = (const float*)d_in[12];
    const float* mw   = (const float*)d_in[13];
    const float* mb   = (const float*)d_in[14];
    float* out = (float*)d_out;

    precompute_kernel<<<8, 128>>>(W1, as1, ad1, W2, as2, ad2, mw, mb, b1, b2);
    gat_main<<<BB, 256>>>(nbr1, nbr2, adj1, adj2, emb, out);
}

// round 3
// speedup vs baseline: 1.6052x; 1.6052x over previous
#include <cuda_runtime.h>

#define BB 64
#define NN 256
#define EE 2048
#define DD 128
#define HH 4
#define LCAP 64
#define NEG_SLOPE 0.2f

// Folded weights + edge-hit lists
__device__ float g_ws[2][HH][DD];   // a_src folded through W
__device__ float g_wd[2][HH][DD];   // a_dst folded through W
__device__ float g_u [2][HH][DD];   // mlp_w slice folded through W^T
__device__ float g_const;
__device__ int   g_cnt [2][BB];
__device__ int   g_list[2][BB][LCAP];   // (edge_pos<<8) | src

__global__ void zero_kernel() {
    int t = threadIdx.x;
    if (t < 2 * BB) ((int*)g_cnt)[t] = 0;
}

// blocks 0-7: fold weights.  blocks 8-263: parallel scan of all edge dsts.
__global__ __launch_bounds__(256)
void prep_kernel(const float* __restrict__ W1, const float* __restrict__ as1,
                 const float* __restrict__ ad1,
                 const float* __restrict__ W2, const float* __restrict__ as2,
                 const float* __restrict__ ad2,
                 const float* __restrict__ mlp_w, const float* __restrict__ mlp_b,
                 const float* __restrict__ b1, const float* __restrict__ b2,
                 const int* __restrict__ adj1, const int* __restrict__ adj2) {
    __shared__ float r0[128], r1[128], r2[128];
    const int tid = threadIdx.x;

    if (blockIdx.x < 8) {
        const int br = blockIdx.x >> 2, h = blockIdx.x & 3;
        const float* W   = br ? W2  : W1;
        const float* as_ = br ? as2 : as1;
        const float* ad_ = br ? ad2 : ad1;
        const float* mw  = mlp_w + br * DD;
        const int k = tid & 127, p = tid >> 7;   // 2-way split over d

        float aws = 0.f, awd = 0.f, au = 0.f;
        #pragma unroll 16
        for (int dd = 0; dd < 64; ++dd) {
            int d = p * 64 + dd;
            float wv = W[(h * DD + d) * DD + k];
            aws += wv * as_[h * DD + d];
            awd += wv * ad_[h * DD + d];
            au  += wv * mw[d];
        }
        if (p == 1) { r0[k] = aws; r1[k] = awd; r2[k] = au; }
        __syncthreads();
        if (p == 0) {
            g_ws[br][h][k] = aws + r0[k];
            g_wd[br][h][k] = awd + r1[k];
            g_u [br][h][k] = au  + r2[k];
        }
        if (blockIdx.x == 0 && tid < 32) {
            float c = 0.f;
            for (int d = tid; d < DD; d += 32)
                c += mlp_w[d] * b1[d] + mlp_w[DD + d] * b2[d];
            #pragma unroll
            for (int o = 16; o; o >>= 1) c += __shfl_xor_sync(0xffffffffu, c, o);
            if (tid == 0) g_const = c + mlp_b[0];
        }
    } else {
        // Scan: 256 blocks * 256 threads * 4 edges = 262144 = 2*64*2048
        int ge  = (blockIdx.x - 8) * 1024 + tid * 4;
        int br  = ge >> 17;           // / (64*2048)
        int rem = ge & 131071;
        int b   = rem >> 11;
        int e   = rem & 2047;
        const int* base = (br ? adj2 : adj1) + (long)b * 2 * EE;
        int4 dv = *(const int4*)(base + EE + e);
        int d4[4] = { dv.x, dv.y, dv.z, dv.w };
        #pragma unroll
        for (int i = 0; i < 4; ++i) {
            if (d4[i] == 0) {
                int s = base[e + i];
                int slot = atomicAdd(&g_cnt[br][b], 1);
                if (slot < LCAP) g_list[br][b][slot] = ((e + i) << 8) | s;
            }
        }
    }
}

__global__ __launch_bounds__(256)
void gat_main(const int* __restrict__ nbr1, const int* __restrict__ nbr2,
              const float* __restrict__ emb, float* __restrict__ out) {
    __shared__ float sws[2][HH][DD], swd[2][HH][DD], su[2][HH][DD];
    __shared__ float s_adst[2][HH];
    __shared__ int   s_list[2][LCAP + 1];
    __shared__ int   s_m[2];
    __shared__ float wM[8][HH], wS[8][HH], wT[8][HH];

    const int b = blockIdx.x, tid = threadIdx.x;
    const int warp = tid >> 5, lane = tid & 31;
    const float NEGINF = __int_as_float(0xff800000);

    // Stage folded weights + hit lists
    for (int i = tid; i < 2 * HH * DD; i += 256) {
        (&sws[0][0][0])[i] = (&g_ws[0][0][0])[i];
        (&swd[0][0][0])[i] = (&g_wd[0][0][0])[i];
        (&su [0][0][0])[i] = (&g_u [0][0][0])[i];
    }
    if (tid < 2 * LCAP) s_list[tid / LCAP][tid % LCAP] = g_list[tid / LCAP][b][tid % LCAP];
    if (tid < 2)        s_m[tid] = min(g_cnt[tid][b], LCAP);
    __syncthreads();

    // Sort hit lists (determinism) + append self-loop last (matches ref concat order)
    if ((tid & 127) == 0) {
        int br = tid >> 7;
        int n = s_m[br];
        for (int i = 1; i < n; ++i) {
            int key = s_list[br][i], j = i - 1;
            while (j >= 0 && s_list[br][j] > key) { s_list[br][j + 1] = s_list[br][j]; --j; }
            s_list[br][j + 1] = key;
        }
        s_list[br][n] = (2048 << 8);   // self-loop: src = 0
        s_m[br] = n + 1;
    }

    // adst for center node (warps 0 and 4, one per branch)
    if ((warp & 3) == 0) {
        int br = warp >> 2;
        const int* nbr = (br ? nbr2 : nbr1) + b * NN;
        const float* x0 = emb + (long)nbr[0] * DD;
        float a0 = 0, a1 = 0, a2 = 0, a3 = 0;
        #pragma unroll
        for (int c = 0; c < 4; ++c) {
            int d = lane + 32 * c;
            float xv = x0[d];
            a0 += xv * swd[br][0][d]; a1 += xv * swd[br][1][d];
            a2 += xv * swd[br][2][d]; a3 += xv * swd[br][3][d];
        }
        #pragma unroll
        for (int o = 16; o; o >>= 1) {
            a0 += __shfl_xor_sync(0xffffffffu, a0, o);
            a1 += __shfl_xor_sync(0xffffffffu, a1, o);
            a2 += __shfl_xor_sync(0xffffffffu, a2, o);
            a3 += __shfl_xor_sync(0xffffffffu, a3, o);
        }
        if (lane == 0) {
            s_adst[br][0] = a0; s_adst[br][1] = a1;
            s_adst[br][2] = a2; s_adst[br][3] = a3;
        }
    }
    __syncthreads();

    // Each warp handles its branch's nodes round-robin with online softmax
    const int br = warp >> 2, wl = warp & 3;
    const int* nbr = (br ? nbr2 : nbr1) + b * NN;
    const float adst0 = s_adst[br][0], adst1 = s_adst[br][1],
                adst2 = s_adst[br][2], adst3 = s_adst[br][3];

    float m[HH], sA[HH], tA[HH];
    #pragma unroll
    for (int h = 0; h < HH; ++h) { m[h] = NEGINF; sA[h] = 0.f; tA[h] = 0.f; }

    const int mm = s_m[br];
    for (int i = wl; i < mm; i += 4) {
        int j = s_list[br][i] & 255;
        const float* x = emb + (long)nbr[j] * DD;
        float a0 = 0, a1 = 0, a2 = 0, a3 = 0;
        float p0 = 0, p1 = 0, p2 = 0, p3 = 0;
        #pragma unroll
        for (int c = 0; c < 4; ++c) {
            int d = lane + 32 * c;
            float xv = x[d];
            a0 += xv * sws[br][0][d]; a1 += xv * sws[br][1][d];
            a2 += xv * sws[br][2][d]; a3 += xv * sws[br][3][d];
            p0 += xv * su [br][0][d]; p1 += xv * su [br][1][d];
            p2 += xv * su [br][2][d]; p3 += xv * su [br][3][d];
        }
        #pragma unroll
        for (int o = 16; o; o >>= 1) {
            a0 += __shfl_xor_sync(0xffffffffu, a0, o);
            a1 += __shfl_xor_sync(0xffffffffu, a1, o);
            a2 += __shfl_xor_sync(0xffffffffu, a2, o);
            a3 += __shfl_xor_sync(0xffffffffu, a3, o);
            p0 += __shfl_xor_sync(0xffffffffu, p0, o);
            p1 += __shfl_xor_sync(0xffffffffu, p1, o);
            p2 += __shfl_xor_sync(0xffffffffu, p2, o);
            p3 += __shfl_xor_sync(0xffffffffu, p3, o);
        }
        float ev[HH] = { a0 + adst0, a1 + adst1, a2 + adst2, a3 + adst3 };
        float pv[HH] = { p0, p1, p2, p3 };
        #pragma unroll
        for (int h = 0; h < HH; ++h) {
            float e = ev[h] > 0.f ? ev[h] : NEG_SLOPE * ev[h];
            float nm = fmaxf(m[h], e);
            float fo = expf(m[h] - nm);
            float fn = expf(e - nm);
            sA[h] = sA[h] * fo + fn;
            tA[h] = tA[h] * fo + pv[h] * fn;
            m[h]  = nm;
        }
    }

    if (lane == 0) {
        #pragma unroll
        for (int h = 0; h < HH; ++h) { wM[warp][h] = m[h]; wS[warp][h] = sA[h]; wT[warp][h] = tA[h]; }
    }
    __syncthreads();

    // Deterministic merge: fixed warp order within each branch
    if (tid == 0) {
        float total = 0.f;
        #pragma unroll
        for (int brx = 0; brx < 2; ++brx) {
            #pragma unroll
            for (int h = 0; h < HH; ++h) {
                float M = NEGINF, S = 0.f, T = 0.f;
                for (int w = 4 * brx; w < 4 * brx + 4; ++w) {
                    float mw_ = wM[w][h], sw_ = wS[w][h], tw_ = wT[w][h];
                    if (sw_ == 0.f) continue;
                    float nm = fmaxf(M, mw_);
                    float fo = expf(M - nm);
                    float fn = expf(mw_ - nm);
                    S = S * fo + sw_ * fn;
                    T = T * fo + tw_ * fn;
                    M = nm;
                }
                total += (T / S) * (1.f / HH);
            }
        }
        out[b] = total + g_const;
    }
}

extern "C" void kernel_launch(void* const* d_in, const int* in_sizes, int n_in,
                              void* d_out, int out_size) {
    const int*   nbr1 = (const int*)  d_in[0];
    const int*   nbr2 = (const int*)  d_in[1];
    const int*   adj1 = (const int*)  d_in[2];
    const int*   adj2 = (const int*)  d_in[3];
    const float* emb  = (const float*)d_in[4];
    const float* W1   = (const float*)d_in[5];
    const float* as1  = (const float*)d_in[6];
    const float* ad1  = (const float*)d_in[7];
    const float* b1   = (const float*)d_in[8];
    const float* W2   = (const float*)d_in[9];
    const float* as2  = (const float*)d_in[10];
    const float* ad2  = (const float*)d_in[11];
    const float* b2   = (const float*)d_in[12];
    const float* mw   = (const float*)d_in[13];
    const float* mb   = (const float*)d_in[14];
    float* out = (float*)d_out;

    zero_kernel<<<1, 128>>>();
    prep_kernel<<<264, 256>>>(W1, as1, ad1, W2, as2, ad2, mw, mb, b1, b2, adj1, adj2);
    gat_main<<<BB, 256>>>(nbr1, nbr2, emb, out);
}

// round 4
// speedup vs baseline: 2.1571x; 1.3438x over previous
#include <cuda_runtime.h>

#define BB 64
#define NN 256
#define EE 2048
#define DD 128
#define HH 4
#define LCAP 64
#define NEG_SLOPE 0.2f

// Folded weights (produced by blocks 0-7, consumed by blocks 8-71)
__device__ float g_ws[2][HH][DD];
__device__ float g_wd[2][HH][DD];
__device__ float g_u [2][HH][DD];
__device__ float g_const;
__device__ int   g_done = 0;   // producers arrived (0..8), reset by last consumer
__device__ int   g_exit = 0;   // consumers finished (0..64), reset by last consumer

__global__ __launch_bounds__(256)
void gat_fused(const float* __restrict__ W1, const float* __restrict__ as1,
               const float* __restrict__ ad1,
               const float* __restrict__ W2, const float* __restrict__ as2,
               const float* __restrict__ ad2,
               const float* __restrict__ mlp_w, const float* __restrict__ mlp_b,
               const float* __restrict__ b1, const float* __restrict__ b2,
               const int* __restrict__ adj1, const int* __restrict__ adj2,
               const int* __restrict__ nbr1, const int* __restrict__ nbr2,
               const float* __restrict__ emb, float* __restrict__ out) {
    const int tid = threadIdx.x;

    // ───────── Producer blocks: fold weights ─────────
    if (blockIdx.x < 8) {
        __shared__ float r0[128], r1[128], r2[128];
        const int br = blockIdx.x >> 2, h = blockIdx.x & 3;
        const float* W   = br ? W2  : W1;
        const float* as_ = br ? as2 : as1;
        const float* ad_ = br ? ad2 : ad1;
        const float* mw  = mlp_w + br * DD;
        const int k = tid & 127, p = tid >> 7;   // 2-way split over d

        float aws = 0.f, awd = 0.f, au = 0.f;
        #pragma unroll 16
        for (int dd = 0; dd < 64; ++dd) {
            int d = p * 64 + dd;
            float wv = W[(h * DD + d) * DD + k];
            aws += wv * as_[h * DD + d];
            awd += wv * ad_[h * DD + d];
            au  += wv * mw[d];
        }
        if (p == 1) { r0[k] = aws; r1[k] = awd; r2[k] = au; }
        __syncthreads();
        if (p == 0) {
            g_ws[br][h][k] = aws + r0[k];
            g_wd[br][h][k] = awd + r1[k];
            g_u [br][h][k] = au  + r2[k];
        }
        if (blockIdx.x == 0 && tid >= 128 && tid < 160) {
            int l = tid - 128;
            float c = 0.f;
            for (int d = l; d < DD; d += 32)
                c += mlp_w[d] * b1[d] + mlp_w[DD + d] * b2[d];
            #pragma unroll
            for (int o = 16; o; o >>= 1) c += __shfl_xor_sync(0xffffffffu, c, o);
            if (l == 0) g_const = c + mlp_b[0];
        }
        __syncthreads();
        if (tid == 0) { __threadfence(); atomicAdd(&g_done, 1); }
        return;
    }

    // ───────── Consumer blocks: one batch each ─────────
    __shared__ float sws[2][HH][DD], swd[2][HH][DD], su[2][HH][DD];
    __shared__ float s_adst[2][HH];
    __shared__ int   s_list[2][LCAP + 1];
    __shared__ int   s_cnt[2];
    __shared__ float wM[8][HH], wS[8][HH], wT[8][HH];

    const int b = blockIdx.x - 8;
    const int warp = tid >> 5, lane = tid & 31;
    const float NEGINF = __int_as_float(0xff800000);

    if (tid < 2) s_cnt[tid] = 0;
    __syncthreads();

    // Parallel scan of this batch's edges: 128 threads per branch, 16 dsts each
    {
        const int brx = tid >> 7, t = tid & 127;
        const int e0 = t * 16;
        const int* base = (brx ? adj2 : adj1) + (long)b * 2 * EE;
        int4 v[4];
        #pragma unroll
        for (int q = 0; q < 4; ++q)
            v[q] = *(const int4*)(base + EE + e0 + 4 * q);
        #pragma unroll
        for (int q = 0; q < 4; ++q) {
            int d4[4] = { v[q].x, v[q].y, v[q].z, v[q].w };
            #pragma unroll
            for (int i = 0; i < 4; ++i) {
                if (d4[i] == 0) {
                    int e = e0 + 4 * q + i;
                    int s = base[e];
                    int slot = atomicAdd(&s_cnt[brx], 1);
                    if (slot < LCAP) s_list[brx][slot] = (e << 8) | s;
                }
            }
        }
    }
    __syncthreads();

    // Sort (determinism) + append self-loop last
    if ((tid & 127) == 0) {
        int brx = tid >> 7;
        int n = min(s_cnt[brx], LCAP);
        for (int i = 1; i < n; ++i) {
            int key = s_list[brx][i], j = i - 1;
            while (j >= 0 && s_list[brx][j] > key) { s_list[brx][j + 1] = s_list[brx][j]; --j; }
            s_list[brx][j + 1] = key;
        }
        s_list[brx][n] = (EE << 8);   // self-loop: src node 0
        s_cnt[brx] = n + 1;
    }

    // Wait for folded weights (fold overlapped the scan, usually already done)
    if (tid == 0) {
        while (atomicAdd(&g_done, 0) < 8) __nanosleep(20);
    }
    __syncthreads();
    __threadfence();

    // Stage folded weights
    for (int i = tid; i < 2 * HH * DD; i += 256) {
        (&sws[0][0][0])[i] = (&g_ws[0][0][0])[i];
        (&swd[0][0][0])[i] = (&g_wd[0][0][0])[i];
        (&su [0][0][0])[i] = (&g_u [0][0][0])[i];
    }
    __syncthreads();

    // adst for center node (warps 0 and 4, one per branch)
    if ((warp & 3) == 0) {
        int brx = warp >> 2;
        const int* nbr = (brx ? nbr2 : nbr1) + b * NN;
        const float* x0 = emb + (long)nbr[0] * DD;
        float a0 = 0, a1 = 0, a2 = 0, a3 = 0;
        #pragma unroll
        for (int c = 0; c < 4; ++c) {
            int d = lane + 32 * c;
            float xv = x0[d];
            a0 += xv * swd[brx][0][d]; a1 += xv * swd[brx][1][d];
            a2 += xv * swd[brx][2][d]; a3 += xv * swd[brx][3][d];
        }
        #pragma unroll
        for (int o = 16; o; o >>= 1) {
            a0 += __shfl_xor_sync(0xffffffffu, a0, o);
            a1 += __shfl_xor_sync(0xffffffffu, a1, o);
            a2 += __shfl_xor_sync(0xffffffffu, a2, o);
            a3 += __shfl_xor_sync(0xffffffffu, a3, o);
        }
        if (lane == 0) {
            s_adst[brx][0] = a0; s_adst[brx][1] = a1;
            s_adst[brx][2] = a2; s_adst[brx][3] = a3;
        }
    }
    __syncthreads();

    // Each warp: its branch's source nodes round-robin, online softmax
    const int br = warp >> 2, wl = warp & 3;
    const int* nbr = (br ? nbr2 : nbr1) + b * NN;
    const float adst0 = s_adst[br][0], adst1 = s_adst[br][1],
                adst2 = s_adst[br][2], adst3 = s_adst[br][3];

    float m[HH], sA[HH], tA[HH];
    #pragma unroll
    for (int h = 0; h < HH; ++h) { m[h] = NEGINF; sA[h] = 0.f; tA[h] = 0.f; }

    const int mm = s_cnt[br];
    for (int i = wl; i < mm; i += 4) {
        int j = s_list[br][i] & 255;
        const float* x = emb + (long)nbr[j] * DD;
        float a0 = 0, a1 = 0, a2 = 0, a3 = 0;
        float p0 = 0, p1 = 0, p2 = 0, p3 = 0;
        #pragma unroll
        for (int c = 0; c < 4; ++c) {
            int d = lane + 32 * c;
            float xv = x[d];
            a0 += xv * sws[br][0][d]; a1 += xv * sws[br][1][d];
            a2 += xv * sws[br][2][d]; a3 += xv * sws[br][3][d];
            p0 += xv * su [br][0][d]; p1 += xv * su [br][1][d];
            p2 += xv * su [br][2][d]; p3 += xv * su [br][3][d];
        }
        #pragma unroll
        for (int o = 16; o; o >>= 1) {
            a0 += __shfl_xor_sync(0xffffffffu, a0, o);
            a1 += __shfl_xor_sync(0xffffffffu, a1, o);
            a2 += __shfl_xor_sync(0xffffffffu, a2, o);
            a3 += __shfl_xor_sync(0xffffffffu, a3, o);
            p0 += __shfl_xor_sync(0xffffffffu, p0, o);
            p1 += __shfl_xor_sync(0xffffffffu, p1, o);
            p2 += __shfl_xor_sync(0xffffffffu, p2, o);
            p3 += __shfl_xor_sync(0xffffffffu, p3, o);
        }
        float ev[HH] = { a0 + adst0, a1 + adst1, a2 + adst2, a3 + adst3 };
        float pv[HH] = { p0, p1, p2, p3 };
        #pragma unroll
        for (int h = 0; h < HH; ++h) {
            float e = ev[h] > 0.f ? ev[h] : NEG_SLOPE * ev[h];
            float nm = fmaxf(m[h], e);
            float fo = expf(m[h] - nm);
            float fn = expf(e - nm);
            sA[h] = sA[h] * fo + fn;
            tA[h] = tA[h] * fo + pv[h] * fn;
            m[h]  = nm;
        }
    }

    if (lane == 0) {
        #pragma unroll
        for (int h = 0; h < HH; ++h) { wM[warp][h] = m[h]; wS[warp][h] = sA[h]; wT[warp][h] = tA[h]; }
    }
    __syncthreads();

    // Deterministic merge (fixed warp order per branch) + output + reset
    if (tid == 0) {
        float total = 0.f;
        #pragma unroll
        for (int brx = 0; brx < 2; ++brx) {
            #pragma unroll
            for (int h = 0; h < HH; ++h) {
                float M = NEGINF, S = 0.f, T = 0.f;
                for (int w = 4 * brx; w < 4 * brx + 4; ++w) {
                    float mw_ = wM[w][h], sw_ = wS[w][h], tw_ = wT[w][h];
                    if (sw_ == 0.f) continue;
                    float nm = fmaxf(M, mw_);
                    float fo = expf(M - nm);
                    float fn = expf(mw_ - nm);
                    S = S * fo + sw_ * fn;
                    T = T * fo + tw_ * fn;
                    M = nm;
                }
                total += (T / S) * (1.f / HH);
            }
        }
        out[b] = total + g_const;

        int fin = atomicAdd(&g_exit, 1);
        if (fin == BB - 1) {      // last consumer resets for next graph replay
            g_done = 0;
            g_exit = 0;
            __threadfence();
        }
    }
}

extern "C" void kernel_launch(void* const* d_in, const int* in_sizes, int n_in,
                              void* d_out, int out_size) {
    const int*   nbr1 = (const int*)  d_in[0];
    const int*   nbr2 = (const int*)  d_in[1];
    const int*   adj1 = (const int*)  d_in[2];
    const int*   adj2 = (const int*)  d_in[3];
    const float* emb  = (const float*)d_in[4];
    const float* W1   = (const float*)d_in[5];
    const float* as1  = (const float*)d_in[6];
    const float* ad1  = (const float*)d_in[7];
    const float* b1   = (const float*)d_in[8];
    const float* W2   = (const float*)d_in[9];
    const float* as2  = (const float*)d_in[10];
    const float* ad2  = (const float*)d_in[11];
    const float* b2   = (const float*)d_in[12];
    const float* mw   = (const float*)d_in[13];
    const float* mb   = (const float*)d_in[14];
    float* out = (float*)d_out;

    gat_fused<<<8 + BB, 256>>>(W1, as1, ad1, W2, as2, ad2, mw, mb, b1, b2,
                               adj1, adj2, nbr1, nbr2, emb, out);
}

// round 5
// speedup vs baseline: 2.2102x; 1.0246x over previous
#include <cuda_runtime.h>

#define BB 64
#define NN 256
#define EE 2048
#define DD 128
#define HH 4
#define LCAP 64
#define XCAP 32
#define NEG_SLOPE 0.2f

// Folded weights (produced by blocks 0-7, consumed by blocks 8-71)
__device__ float g_ws[2][HH][DD];
__device__ float g_wd[2][HH][DD];
__device__ float g_u [2][HH][DD];
__device__ float g_const;
__device__ int   g_done = 0;   // producers arrived (0..8)
__device__ int   g_pass = 0;   // consumers past the wait (0..64); 64th resets both

__global__ __launch_bounds__(256)
void gat_fused(const float* __restrict__ W1, const float* __restrict__ as1,
               const float* __restrict__ ad1,
               const float* __restrict__ W2, const float* __restrict__ as2,
               const float* __restrict__ ad2,
               const float* __restrict__ mlp_w, const float* __restrict__ mlp_b,
               const float* __restrict__ b1, const float* __restrict__ b2,
               const int* __restrict__ adj1, const int* __restrict__ adj2,
               const int* __restrict__ nbr1, const int* __restrict__ nbr2,
               const float* __restrict__ emb, float* __restrict__ out) {
    const int tid = threadIdx.x;

    // ───────── Producer blocks: fold weights ─────────
    if (blockIdx.x < 8) {
        __shared__ float r0[128], r1[128], r2[128];
        const int br = blockIdx.x >> 2, h = blockIdx.x & 3;
        const float* W   = br ? W2  : W1;
        const float* as_ = br ? as2 : as1;
        const float* ad_ = br ? ad2 : ad1;
        const float* mw  = mlp_w + br * DD;
        const int k = tid & 127, p = tid >> 7;   // 2-way split over d

        float aws = 0.f, awd = 0.f, au = 0.f;
        #pragma unroll
        for (int dd = 0; dd < 64; ++dd) {
            int d = p * 64 + dd;
            float wv = W[(h * DD + d) * DD + k];
            aws += wv * as_[h * DD + d];
            awd += wv * ad_[h * DD + d];
            au  += wv * mw[d];
        }
        if (p == 1) { r0[k] = aws; r1[k] = awd; r2[k] = au; }
        __syncthreads();
        if (p == 0) {
            g_ws[br][h][k] = aws + r0[k];
            g_wd[br][h][k] = awd + r1[k];
            g_u [br][h][k] = au  + r2[k];
        }
        if (blockIdx.x == 0 && tid >= 128 && tid < 160) {
            int l = tid - 128;
            float c = 0.f;
            for (int d = l; d < DD; d += 32)
                c += mlp_w[d] * b1[d] + mlp_w[DD + d] * b2[d];
            #pragma unroll
            for (int o = 16; o; o >>= 1) c += __shfl_xor_sync(0xffffffffu, c, o);
            if (l == 0) g_const = c + mlp_b[0];
        }
        __syncthreads();
        if (tid == 0) { __threadfence(); atomicAdd(&g_done, 1); }
        return;
    }

    // ───────── Consumer blocks: one batch each ─────────
    __shared__ float sws[2][HH][DD], swd[2][HH][DD], su[2][HH][DD];  // 12 KB
    __shared__ float s_x[2][XCAP][DD];                               // 32 KB node rows
    __shared__ float s_adst[2][HH];
    __shared__ int   s_list[2][LCAP + 1];
    __shared__ int   s_cnt[2];
    __shared__ int   s_tot[2];
    __shared__ float wM[8][HH], wS[8][HH], wT[8][HH];

    const int b = blockIdx.x - 8;
    const int warp = tid >> 5, lane = tid & 31;
    const float NEGINF = __int_as_float(0xff800000);

    if (tid < 2) s_cnt[tid] = 0;
    __syncthreads();

    // Parallel scan: 128 threads per branch, 16 edges each; src+dst loaded together
    {
        const int brx = tid >> 7, t = tid & 127;
        const int e0 = t * 16;
        const int* base = (brx ? adj2 : adj1) + (long)b * 2 * EE;
        int4 vd[4], vs[4];
        #pragma unroll
        for (int q = 0; q < 4; ++q) {
            vd[q] = *(const int4*)(base + EE + e0 + 4 * q);   // dst
            vs[q] = *(const int4*)(base +      e0 + 4 * q);   // src
        }
        #pragma unroll
        for (int q = 0; q < 4; ++q) {
            int d4[4] = { vd[q].x, vd[q].y, vd[q].z, vd[q].w };
            int s4[4] = { vs[q].x, vs[q].y, vs[q].z, vs[q].w };
            #pragma unroll
            for (int i = 0; i < 4; ++i) {
                if (d4[i] == 0) {
                    int slot = atomicAdd(&s_cnt[brx], 1);
                    if (slot < LCAP) s_list[brx][slot] = ((e0 + 4 * q + i) << 8) | s4[i];
                }
            }
        }
    }
    __syncthreads();

    // Sort (determinism, ref edge order) + append self-loop last
    if ((tid & 127) == 0) {
        int brx = tid >> 7;
        int n = min(s_cnt[brx], LCAP);
        for (int i = 1; i < n; ++i) {
            int key = s_list[brx][i], j = i - 1;
            while (j >= 0 && s_list[brx][j] > key) { s_list[brx][j + 1] = s_list[brx][j]; --j; }
            s_list[brx][j + 1] = key;
        }
        s_list[brx][n] = (EE << 8);   // self-loop: src node 0 (== center)
        s_tot[brx] = n + 1;
    }
    __syncthreads();

    // Prefetch all node rows into smem: one row per warp round, one float4 per lane.
    // Overlaps the producer wait below.
    {
        const int n0 = s_tot[0], n1 = s_tot[1];
        const int total = n0 + n1;
        for (int i = warp; i < total; i += 8) {
            const int brx = (i >= n0) ? 1 : 0;
            const int li  = brx ? (i - n0) : i;
            if (li < XCAP) {
                const int j = s_list[brx][li] & 255;
                const int* nbr = (brx ? nbr2 : nbr1) + b * NN;
                const float4 v = *(const float4*)(emb + (long)nbr[j] * DD + lane * 4);
                *(float4*)&s_x[brx][li][lane * 4] = v;
            }
        }
    }

    // Wait for folded weights — volatile load poll (no RMW contention)
    if (tid == 0) {
        const volatile int* pd = &g_done;
        while (*pd < 8) __nanosleep(64);
        int fin = atomicAdd(&g_pass, 1);     // off the exit critical path
        if (fin == BB - 1) { g_done = 0; g_pass = 0; __threadfence(); }
    }
    __syncthreads();

    // Stage folded weights (L2 hits; producers just wrote them)
    for (int i = tid; i < 2 * HH * DD; i += 256) {
        (&sws[0][0][0])[i] = (&g_ws[0][0][0])[i];
        (&swd[0][0][0])[i] = (&g_wd[0][0][0])[i];
        (&su [0][0][0])[i] = (&g_u [0][0][0])[i];
    }
    __syncthreads();

    // adst for center node (warps 0 and 4). Center row == self-loop slot (src=0 -> nbr[0]).
    if ((warp & 3) == 0) {
        int brx = warp >> 2;
        int sl = s_tot[brx] - 1;                 // self-loop slot (src node 0)
        const float* x0 = (sl < XCAP) ? &s_x[brx][sl][0]
                                      : emb + (long)((brx ? nbr2 : nbr1)[b * NN]) * DD;
        float a0 = 0, a1 = 0, a2 = 0, a3 = 0;
        #pragma unroll
        for (int c = 0; c < 4; ++c) {
            int d = lane + 32 * c;
            float xv = x0[d];
            a0 += xv * swd[brx][0][d]; a1 += xv * swd[brx][1][d];
            a2 += xv * swd[brx][2][d]; a3 += xv * swd[brx][3][d];
        }
        #pragma unroll
        for (int o = 16; o; o >>= 1) {
            a0 += __shfl_xor_sync(0xffffffffu, a0, o);
            a1 += __shfl_xor_sync(0xffffffffu, a1, o);
            a2 += __shfl_xor_sync(0xffffffffu, a2, o);
            a3 += __shfl_xor_sync(0xffffffffu, a3, o);
        }
        if (lane == 0) {
            s_adst[brx][0] = a0; s_adst[brx][1] = a1;
            s_adst[brx][2] = a2; s_adst[brx][3] = a3;
        }
    }
    __syncthreads();

    // Each warp: its branch's nodes round-robin, online softmax, smem-only loads
    const int br = warp >> 2, wl = warp & 3;
    const int* nbr = (br ? nbr2 : nbr1) + b * NN;
    const float adst0 = s_adst[br][0], adst1 = s_adst[br][1],
                adst2 = s_adst[br][2], adst3 = s_adst[br][3];

    float m[HH], sA[HH], tA[HH];
    #pragma unroll
    for (int h = 0; h < HH; ++h) { m[h] = NEGINF; sA[h] = 0.f; tA[h] = 0.f; }

    const int mm = s_tot[br];
    for (int i = wl; i < mm; i += 4) {
        const float* x = (i < XCAP) ? &s_x[br][i][0]
                                    : emb + (long)nbr[s_list[br][i] & 255] * DD;
        float a0 = 0, a1 = 0, a2 = 0, a3 = 0;
        float p0 = 0, p1 = 0, p2 = 0, p3 = 0;
        #pragma unroll
        for (int c = 0; c < 4; ++c) {
            int d = lane + 32 * c;
            float xv = x[d];
            a0 += xv * sws[br][0][d]; a1 += xv * sws[br][1][d];
            a2 += xv * sws[br][2][d]; a3 += xv * sws[br][3][d];
            p0 += xv * su [br][0][d]; p1 += xv * su [br][1][d];
            p2 += xv * su [br][2][d]; p3 += xv * su [br][3][d];
        }
        #pragma unroll
        for (int o = 16; o; o >>= 1) {
            a0 += __shfl_xor_sync(0xffffffffu, a0, o);
            a1 += __shfl_xor_sync(0xffffffffu, a1, o);
            a2 += __shfl_xor_sync(0xffffffffu, a2, o);
            a3 += __shfl_xor_sync(0xffffffffu, a3, o);
            p0 += __shfl_xor_sync(0xffffffffu, p0, o);
            p1 += __shfl_xor_sync(0xffffffffu, p1, o);
            p2 += __shfl_xor_sync(0xffffffffu, p2, o);
            p3 += __shfl_xor_sync(0xffffffffu, p3, o);
        }
        float ev[HH] = { a0 + adst0, a1 + adst1, a2 + adst2, a3 + adst3 };
        float pv[HH] = { p0, p1, p2, p3 };
        #pragma unroll
        for (int h = 0; h < HH; ++h) {
            float e = ev[h] > 0.f ? ev[h] : NEG_SLOPE * ev[h];
            float nm = fmaxf(m[h], e);
            float fo = expf(m[h] - nm);
            float fn = expf(e - nm);
            sA[h] = sA[h] * fo + fn;
            tA[h] = tA[h] * fo + pv[h] * fn;
            m[h]  = nm;
        }
    }

    if (lane == 0) {
        #pragma unroll
        for (int h = 0; h < HH; ++h) { wM[warp][h] = m[h]; wS[warp][h] = sA[h]; wT[warp][h] = tA[h]; }
    }
    __syncthreads();

    // Deterministic merge (fixed warp order per branch) + output
    if (tid == 0) {
        float total = 0.f;
        #pragma unroll
        for (int brx = 0; brx < 2; ++brx) {
            #pragma unroll
            for (int h = 0; h < HH; ++h) {
                float M = NEGINF, S = 0.f, T = 0.f;
                for (int w = 4 * brx; w < 4 * brx + 4; ++w) {
                    float mw_ = wM[w][h], sw_ = wS[w][h], tw_ = wT[w][h];
                    if (sw_ == 0.f) continue;
                    float nm = fmaxf(M, mw_);
                    float fo = expf(M - nm);
                    float fn = expf(mw_ - nm);
                    S = S * fo + sw_ * fn;
                    T = T * fo + tw_ * fn;
                    M = nm;
                }
                total += (T / S) * (1.f / HH);
            }
        }
        out[b] = total + g_const;
    }
}

extern "C" void kernel_launch(void* const* d_in, const int* in_sizes, int n_in,
                              void* d_out, int out_size) {
    const int*   nbr1 = (const int*)  d_in[0];
    const int*   nbr2 = (const int*)  d_in[1];
    const int*   adj1 = (const int*)  d_in[2];
    const int*   adj2 = (const int*)  d_in[3];
    const float* emb  = (const float*)d_in[4];
    const float* W1   = (const float*)d_in[5];
    const float* as1  = (const float*)d_in[6];
    const float* ad1  = (const float*)d_in[7];
    const float* b1   = (const float*)d_in[8];
    const float* W2   = (const float*)d_in[9];
    const float* as2  = (const float*)d_in[10];
    const float* ad2  = (const float*)d_in[11];
    const float* b2   = (const float*)d_in[12];
    const float* mw   = (const float*)d_in[13];
    const float* mb   = (const float*)d_in[14];
    float* out = (float*)d_out;

    gat_fused<<<8 + BB, 256>>>(W1, as1, ad1, W2, as2, ad2, mw, mb, b1, b2,
                               adj1, adj2, nbr1, nbr2, emb, out);
}

// round 6
// speedup vs baseline: 2.4777x; 1.1210x over previous
#include <cuda_runtime.h>

#define BB 64
#define NN 256
#define EE 2048
#define DD 128
#define HH 4
#define LCAP 64
#define XCAP 32
#define NEG_SLOPE 0.2f

// Folded weights (produced by blocks 0-7, consumed by blocks 8-71)
__device__ float g_ws[2][HH][DD];
__device__ float g_wd[2][HH][DD];
__device__ float g_u [2][HH][DD];
__device__ float g_const;
__device__ int   g_done = 0;   // producers arrived (0..8)
__device__ int   g_pass = 0;   // consumers past the wait; 64th resets both

__global__ __launch_bounds__(256)
void gat_fused(const float* __restrict__ W1, const float* __restrict__ as1,
               const float* __restrict__ ad1,
               const float* __restrict__ W2, const float* __restrict__ as2,
               const float* __restrict__ ad2,
               const float* __restrict__ mlp_w, const float* __restrict__ mlp_b,
               const float* __restrict__ b1, const float* __restrict__ b2,
               const int* __restrict__ adj1, const int* __restrict__ adj2,
               const int* __restrict__ nbr1, const int* __restrict__ nbr2,
               const float* __restrict__ emb, float* __restrict__ out) {
    const int tid = threadIdx.x;

    // ───────── Producer blocks: fold weights ─────────
    if (blockIdx.x < 8) {
        __shared__ float r0[128], r1[128], r2[128];
        const int br = blockIdx.x >> 2, h = blockIdx.x & 3;
        const float* W   = br ? W2  : W1;
        const float* as_ = br ? as2 : as1;
        const float* ad_ = br ? ad2 : ad1;
        const float* mw  = mlp_w + br * DD;
        const int k = tid & 127, p = tid >> 7;   // 2-way split over d

        float aws = 0.f, awd = 0.f, au = 0.f;
        #pragma unroll
        for (int dd = 0; dd < 64; ++dd) {
            int d = p * 64 + dd;
            float wv = W[(h * DD + d) * DD + k];
            aws += wv * as_[h * DD + d];
            awd += wv * ad_[h * DD + d];
            au  += wv * mw[d];
        }
        if (p == 1) { r0[k] = aws; r1[k] = awd; r2[k] = au; }
        __syncthreads();
        if (p == 0) {
            g_ws[br][h][k] = aws + r0[k];
            g_wd[br][h][k] = awd + r1[k];
            g_u [br][h][k] = au  + r2[k];
        }
        if (blockIdx.x == 0 && tid >= 128 && tid < 160) {
            int l = tid - 128;
            float c = 0.f;
            for (int d = l; d < DD; d += 32)
                c += mlp_w[d] * b1[d] + mlp_w[DD + d] * b2[d];
            #pragma unroll
            for (int o = 16; o; o >>= 1) c += __shfl_xor_sync(0xffffffffu, c, o);
            if (l == 0) g_const = c + mlp_b[0];
        }
        __syncthreads();
        if (tid == 0) { __threadfence(); atomicAdd(&g_done, 1); }
        return;
    }

    // ───────── Consumer blocks: one batch each ─────────
    __shared__ float sws[2][HH][DD], swd[2][HH][DD], su[2][HH][DD];  // 12 KB
    __shared__ float s_x[2][XCAP][DD];                               // 32 KB node rows
    __shared__ int   s_nbr[2][NN];                                   // 2 KB
    __shared__ int   s_list[2][LCAP + 1];
    __shared__ int   s_cnt[2];
    __shared__ int   s_tot[2];
    __shared__ float wM[8][HH], wS[8][HH], wT[8][HH];

    const int b = blockIdx.x - 8;
    const int warp = tid >> 5, lane = tid & 31;
    const float NEGINF = __int_as_float(0xff800000);

    if (tid < 2) s_cnt[tid] = 0;
    __syncthreads();

    // Stage nbr rows into smem (independent of scan — loads overlap).
    {
        int i0 = tid;               // 0..255 -> branch 0
        s_nbr[0][i0] = nbr1[b * NN + i0];
        s_nbr[1][i0] = nbr2[b * NN + i0];
    }

    // Parallel scan: 128 threads per branch, 16 edges each; src+dst loaded together
    {
        const int brx = tid >> 7, t = tid & 127;
        const int e0 = t * 16;
        const int* base = (brx ? adj2 : adj1) + (long)b * 2 * EE;
        int4 vd[4], vs[4];
        #pragma unroll
        for (int q = 0; q < 4; ++q) {
            vd[q] = *(const int4*)(base + EE + e0 + 4 * q);   // dst
            vs[q] = *(const int4*)(base +      e0 + 4 * q);   // src
        }
        #pragma unroll
        for (int q = 0; q < 4; ++q) {
            int d4[4] = { vd[q].x, vd[q].y, vd[q].z, vd[q].w };
            int s4[4] = { vs[q].x, vs[q].y, vs[q].z, vs[q].w };
            #pragma unroll
            for (int i = 0; i < 4; ++i) {
                if (d4[i] == 0) {
                    int slot = atomicAdd(&s_cnt[brx], 1);
                    if (slot < LCAP) s_list[brx][slot] = ((e0 + 4 * q + i) << 8) | s4[i];
                }
            }
        }
    }
    __syncthreads();

    // Sort (determinism, ref edge order) + append self-loop last
    if ((tid & 127) == 0) {
        int brx = tid >> 7;
        int n = min(s_cnt[brx], LCAP);
        for (int i = 1; i < n; ++i) {
            int key = s_list[brx][i], j = i - 1;
            while (j >= 0 && s_list[brx][j] > key) { s_list[brx][j + 1] = s_list[brx][j]; --j; }
            s_list[brx][j + 1] = key;
        }
        s_list[brx][n] = (EE << 8);   // self-loop: src node 0 (== center)
        s_tot[brx] = n + 1;
    }
    __syncthreads();

    // Prefetch node rows into smem (nbr index now comes from smem — single
    // dependent global round). One row per warp round, one float4 per lane.
    {
        const int n0 = s_tot[0], n1 = s_tot[1];
        const int total = n0 + n1;
        for (int i = warp; i < total; i += 8) {
            const int brx = (i >= n0) ? 1 : 0;
            const int li  = brx ? (i - n0) : i;
            if (li < XCAP) {
                const int j = s_list[brx][li] & 255;
                const float4 v = *(const float4*)(emb + (long)s_nbr[brx][j] * DD + lane * 4);
                *(float4*)&s_x[brx][li][lane * 4] = v;
            }
        }
    }

    // Wait for folded weights — tight volatile spin (usually already satisfied)
    if (tid == 0) {
        const volatile int* pd = &g_done;
        while (*pd < 8) {}
        int fin = atomicAdd(&g_pass, 1);
        if (fin == BB - 1) { g_done = 0; g_pass = 0; __threadfence(); }
    }
    __syncthreads();
    __threadfence();

    // Stage folded weights (L2 hits)
    for (int i = tid; i < 2 * HH * DD; i += 256) {
        (&sws[0][0][0])[i] = (&g_ws[0][0][0])[i];
        (&swd[0][0][0])[i] = (&g_wd[0][0][0])[i];
        (&su [0][0][0])[i] = (&g_u [0][0][0])[i];
    }
    __syncthreads();

    // Each warp: compute adst redundantly (no cross-warp sync), then its
    // branch's nodes round-robin with online softmax. All smem-resident.
    const int br = warp >> 2, wl = warp & 3;
    const int mm = s_tot[br];
    const int sl = mm - 1;                 // self-loop slot == center row

    float adst0, adst1, adst2, adst3;
    {
        const float* x0 = (sl < XCAP) ? &s_x[br][sl][0]
                                      : emb + (long)s_nbr[br][0] * DD;
        float a0 = 0, a1 = 0, a2 = 0, a3 = 0;
        #pragma unroll
        for (int c = 0; c < 4; ++c) {
            int d = lane + 32 * c;
            float xv = x0[d];
            a0 += xv * swd[br][0][d]; a1 += xv * swd[br][1][d];
            a2 += xv * swd[br][2][d]; a3 += xv * swd[br][3][d];
        }
        #pragma unroll
        for (int o = 16; o; o >>= 1) {
            a0 += __shfl_xor_sync(0xffffffffu, a0, o);
            a1 += __shfl_xor_sync(0xffffffffu, a1, o);
            a2 += __shfl_xor_sync(0xffffffffu, a2, o);
            a3 += __shfl_xor_sync(0xffffffffu, a3, o);
        }
        adst0 = a0; adst1 = a1; adst2 = a2; adst3 = a3;
    }

    float m[HH], sA[HH], tA[HH];
    #pragma unroll
    for (int h = 0; h < HH; ++h) { m[h] = NEGINF; sA[h] = 0.f; tA[h] = 0.f; }

    for (int i = wl; i < mm; i += 4) {
        const float* x = (i < XCAP) ? &s_x[br][i][0]
                                    : emb + (long)s_nbr[br][s_list[br][i] & 255] * DD;
        float a0 = 0, a1 = 0, a2 = 0, a3 = 0;
        float p0 = 0, p1 = 0, p2 = 0, p3 = 0;
        #pragma unroll
        for (int c = 0; c < 4; ++c) {
            int d = lane + 32 * c;
            float xv = x[d];
            a0 += xv * sws[br][0][d]; a1 += xv * sws[br][1][d];
            a2 += xv * sws[br][2][d]; a3 += xv * sws[br][3][d];
            p0 += xv * su [br][0][d]; p1 += xv * su [br][1][d];
            p2 += xv * su [br][2][d]; p3 += xv * su [br][3][d];
        }
        #pragma unroll
        for (int o = 16; o; o >>= 1) {
            a0 += __shfl_xor_sync(0xffffffffu, a0, o);
            a1 += __shfl_xor_sync(0xffffffffu, a1, o);
            a2 += __shfl_xor_sync(0xffffffffu, a2, o);
            a3 += __shfl_xor_sync(0xffffffffu, a3, o);
            p0 += __shfl_xor_sync(0xffffffffu, p0, o);
            p1 += __shfl_xor_sync(0xffffffffu, p1, o);
            p2 += __shfl_xor_sync(0xffffffffu, p2, o);
            p3 += __shfl_xor_sync(0xffffffffu, p3, o);
        }
        float ev[HH] = { a0 + adst0, a1 + adst1, a2 + adst2, a3 + adst3 };
        float pv[HH] = { p0, p1, p2, p3 };
        #pragma unroll
        for (int h = 0; h < HH; ++h) {
            float e = ev[h] > 0.f ? ev[h] : NEG_SLOPE * ev[h];
            float nm = fmaxf(m[h], e);
            float fo = __expf(m[h] - nm);
            float fn = __expf(e - nm);
            sA[h] = sA[h] * fo + fn;
            tA[h] = tA[h] * fo + pv[h] * fn;
            m[h]  = nm;
        }
    }

    if (lane == 0) {
        #pragma unroll
        for (int h = 0; h < HH; ++h) { wM[warp][h] = m[h]; wS[warp][h] = sA[h]; wT[warp][h] = tA[h]; }
    }
    __syncthreads();

    // Parallel deterministic merge: warp 0 lanes 0..7, one (branch, head) each.
    if (warp == 0) {
        float val = 0.f;
        if (lane < 8) {
            const int brx = lane >> 2, h = lane & 3;
            float M = NEGINF, S = 0.f, T = 0.f;
            #pragma unroll
            for (int w = 4 * brx; w < 4 * brx + 4; ++w) {
                float mw_ = wM[w][h], sw_ = wS[w][h], tw_ = wT[w][h];
                if (sw_ != 0.f) {
                    float nm = fmaxf(M, mw_);
                    float fo = __expf(M - nm);
                    float fn = __expf(mw_ - nm);
                    S = S * fo + sw_ * fn;
                    T = T * fo + tw_ * fn;
                    M = nm;
                }
            }
            val = __fdividef(T, S) * (1.f / HH);
        }
        // width-8 tree reduce (fixed order -> deterministic)
        #pragma unroll
        for (int o = 4; o; o >>= 1) val += __shfl_xor_sync(0xffffffffu, val, o);
        if (lane == 0) out[b] = val + g_const;
    }
}

extern "C" void kernel_launch(void* const* d_in, const int* in_sizes, int n_in,
                              void* d_out, int out_size) {
    const int*   nbr1 = (const int*)  d_in[0];
    const int*   nbr2 = (const int*)  d_in[1];
    const int*   adj1 = (const int*)  d_in[2];
    const int*   adj2 = (const int*)  d_in[3];
    const float* emb  = (const float*)d_in[4];
    const float* W1   = (const float*)d_in[5];
    const float* as1  = (const float*)d_in[6];
    const float* ad1  = (const float*)d_in[7];
    const float* b1   = (const float*)d_in[8];
    const float* W2   = (const float*)d_in[9];
    const float* as2  = (const float*)d_in[10];
    const float* ad2  = (const float*)d_in[11];
    const float* b2   = (const float*)d_in[12];
    const float* mw   = (const float*)d_in[13];
    const float* mb   = (const float*)d_in[14];
    float* out = (float*)d_out;

    gat_fused<<<8 + BB, 256>>>(W1, as1, ad1, W2, as2, ad2, mw, mb, b1, b2,
                               adj1, adj2, nbr1, nbr2, emb, out);
}

// round 7
// speedup vs baseline: 2.5933x; 1.0467x over previous
#include <cuda_runtime.h>

#define BB 64
#define NN 256
#define EE 2048
#define DD 128
#define HH 4
#define LCAP 64
#define XCAP 32
#define NEG_SLOPE 0.2f

// Folded weights (produced by blocks 0-7, consumed by blocks 8-71)
__device__ float g_ws[2][HH][DD];
__device__ float g_wd[2][HH][DD];
__device__ float g_u [2][HH][DD];
__device__ float g_const;
__device__ int   g_done = 0;   // producers arrived (0..8)
__device__ int   g_pass = 0;   // consumers past the wait; 64th resets both

__global__ __launch_bounds__(256)
void gat_fused(const float* __restrict__ W1, const float* __restrict__ as1,
               const float* __restrict__ ad1,
               const float* __restrict__ W2, const float* __restrict__ as2,
               const float* __restrict__ ad2,
               const float* __restrict__ mlp_w, const float* __restrict__ mlp_b,
               const float* __restrict__ b1, const float* __restrict__ b2,
               const int* __restrict__ adj1, const int* __restrict__ adj2,
               const int* __restrict__ nbr1, const int* __restrict__ nbr2,
               const float* __restrict__ emb, float* __restrict__ out) {
    const int tid = threadIdx.x;

    // ───────── Producer blocks: fold weights ─────────
    if (blockIdx.x < 8) {
        __shared__ float r0[128], r1[128], r2[128];
        const int br = blockIdx.x >> 2, h = blockIdx.x & 3;
        const float* W   = br ? W2  : W1;
        const float* as_ = br ? as2 : as1;
        const float* ad_ = br ? ad2 : ad1;
        const float* mw  = mlp_w + br * DD;
        const int k = tid & 127, p = tid >> 7;   // 2-way split over d

        float aws = 0.f, awd = 0.f, au = 0.f;
        #pragma unroll
        for (int dd = 0; dd < 64; ++dd) {
            int d = p * 64 + dd;
            float wv = W[(h * DD + d) * DD + k];
            aws += wv * as_[h * DD + d];
            awd += wv * ad_[h * DD + d];
            au  += wv * mw[d];
        }
        if (p == 1) { r0[k] = aws; r1[k] = awd; r2[k] = au; }
        __syncthreads();
        if (p == 0) {
            g_ws[br][h][k] = aws + r0[k];
            g_wd[br][h][k] = awd + r1[k];
            g_u [br][h][k] = au  + r2[k];
        }
        if (blockIdx.x == 0 && tid >= 128 && tid < 160) {
            int l = tid - 128;
            float c = 0.f;
            for (int d = l; d < DD; d += 32)
                c += mlp_w[d] * b1[d] + mlp_w[DD + d] * b2[d];
            #pragma unroll
            for (int o = 16; o; o >>= 1) c += __shfl_xor_sync(0xffffffffu, c, o);
            if (l == 0) g_const = c + mlp_b[0];
        }
        __syncthreads();
        if (tid == 0) { __threadfence(); atomicAdd(&g_done, 1); }
        return;
    }

    // ───────── Consumer blocks: one batch each ─────────
    __shared__ float sws[2][HH][DD], swd[2][HH][DD], su[2][HH][DD];  // 12 KB
    __shared__ float s_x[2][XCAP + 1][DD];   // node rows; row XCAP = center node
    __shared__ int   s_nbr[2][NN];
    __shared__ int   s_list[2][LCAP];        // arrival order:  e<<14 | slot<<8 | src
    __shared__ int   s_sorted[2][LCAP + 1];  // edge order + self-loop last
    __shared__ int   s_cnt[2];
    __shared__ int   s_tot[2];
    __shared__ float wM[8][HH], wS[8][HH], wT[8][HH];

    const int b = blockIdx.x - 8;
    const int warp = tid >> 5, lane = tid & 31;
    const float NEGINF = __int_as_float(0xff800000);

    if (tid < 2) s_cnt[tid] = 0;
    __syncthreads();

    // Stage nbr rows (independent loads — overlap the scan)
    s_nbr[0][tid] = nbr1[b * NN + tid];
    s_nbr[1][tid] = nbr2[b * NN + tid];

    // Parallel scan: 128 threads per branch, 16 edges each; src+dst together
    {
        const int brx = tid >> 7, t = tid & 127;
        const int e0 = t * 16;
        const int* base = (brx ? adj2 : adj1) + (long)b * 2 * EE;
        int4 vd[4], vs[4];
        #pragma unroll
        for (int q = 0; q < 4; ++q) {
            vd[q] = *(const int4*)(base + EE + e0 + 4 * q);
            vs[q] = *(const int4*)(base +      e0 + 4 * q);
        }
        #pragma unroll
        for (int q = 0; q < 4; ++q) {
            int d4[4] = { vd[q].x, vd[q].y, vd[q].z, vd[q].w };
            int s4[4] = { vs[q].x, vs[q].y, vs[q].z, vs[q].w };
            #pragma unroll
            for (int i = 0; i < 4; ++i) {
                if (d4[i] == 0) {
                    int slot = atomicAdd(&s_cnt[brx], 1);
                    if (slot < LCAP)
                        s_list[brx][slot] = ((e0 + 4 * q + i) << 14) | (slot << 8) | s4[i];
                }
            }
        }
    }
    __syncthreads();

    // Warps 1-7: issue ALL emb gathers (slot order, independent of sort).
    // Warp 0: sort into s_sorted (lanes 0/16, one branch each), then poll weights.
    // Sort + poll latency hides under the gather DRAM round.
    if (warp > 0) {
        const int minc0 = min(min(s_cnt[0], LCAP), XCAP) + 1;   // +1 = center row
        const int minc1 = min(min(s_cnt[1], LCAP), XCAP) + 1;
        for (int i = warp - 1; i < minc0 + minc1; i += 7) {
            const int brx = (i >= minc0) ? 1 : 0;
            const int li  = brx ? (i - minc0) : i;
            const int cc  = brx ? minc1 : minc0;
            int row, src;
            if (li == cc - 1) { row = XCAP; src = 0; }            // center node
            else             { row = li;   src = s_list[brx][li] & 255; }
            const float4 v = *(const float4*)(emb + (long)s_nbr[brx][src] * DD + lane * 4);
            *(float4*)&s_x[brx][row][lane * 4] = v;
        }
    } else {
        if (lane == 0 || lane == 16) {
            const int brx = lane >> 4;
            const int n = min(s_cnt[brx], LCAP);
            for (int i = 0; i < n; ++i) {
                int key = s_list[brx][i], j = i - 1;
                while (j >= 0 && s_sorted[brx][j] > key) { s_sorted[brx][j + 1] = s_sorted[brx][j]; --j; }
                s_sorted[brx][j + 1] = key;
            }
            s_sorted[brx][n] = (EE << 14) | (XCAP << 8);   // self-loop: center row, src 0
            s_tot[brx] = n + 1;
        }
        __syncwarp();
        if (lane == 0) {
            const volatile int* pd = &g_done;
            while (*pd < 8) {}
            __threadfence();
            int fin = atomicAdd(&g_pass, 1);
            if (fin == BB - 1) { g_done = 0; g_pass = 0; __threadfence(); }
        }
    }
    __syncthreads();

    // Stage folded weights: exactly one float4 per thread per array (L2 hits)
    {
        float4* dws = (float4*)&sws[0][0][0];
        float4* dwd = (float4*)&swd[0][0][0];
        float4* dsu = (float4*)&su [0][0][0];
        const float4* gws4 = (const float4*)&g_ws[0][0][0];
        const float4* gwd4 = (const float4*)&g_wd[0][0][0];
        const float4* gsu4 = (const float4*)&g_u [0][0][0];
        dws[tid] = gws4[tid];
        dwd[tid] = gwd4[tid];
        dsu[tid] = gsu4[tid];
    }
    __syncthreads();

    // Per-warp: adst (redundant, no sync), then nodes round-robin + online softmax
    const int br = warp >> 2, wl = warp & 3;
    const int mm = s_tot[br];

    float adst0, adst1, adst2, adst3;
    {
        const float* x0 = &s_x[br][XCAP][0];   // center row, always prefetched
        float a0 = 0, a1 = 0, a2 = 0, a3 = 0;
        #pragma unroll
        for (int c = 0; c < 4; ++c) {
            int d = lane + 32 * c;
            float xv = x0[d];
            a0 += xv * swd[br][0][d]; a1 += xv * swd[br][1][d];
            a2 += xv * swd[br][2][d]; a3 += xv * swd[br][3][d];
        }
        #pragma unroll
        for (int o = 16; o; o >>= 1) {
            a0 += __shfl_xor_sync(0xffffffffu, a0, o);
            a1 += __shfl_xor_sync(0xffffffffu, a1, o);
            a2 += __shfl_xor_sync(0xffffffffu, a2, o);
            a3 += __shfl_xor_sync(0xffffffffu, a3, o);
        }
        adst0 = a0; adst1 = a1; adst2 = a2; adst3 = a3;
    }

    float m[HH], sA[HH], tA[HH];
    #pragma unroll
    for (int h = 0; h < HH; ++h) { m[h] = NEGINF; sA[h] = 0.f; tA[h] = 0.f; }

    for (int i = wl; i < mm; i += 4) {
        const int entry = s_sorted[br][i];
        const int row = (entry >> 8) & 63;
        const float* x = (row <= XCAP) ? &s_x[br][row][0]
                                       : emb + (long)s_nbr[br][entry & 255] * DD;
        float a0 = 0, a1 = 0, a2 = 0, a3 = 0;
        float p0 = 0, p1 = 0, p2 = 0, p3 = 0;
        #pragma unroll
        for (int c = 0; c < 4; ++c) {
            int d = lane + 32 * c;
            float xv = x[d];
            a0 += xv * sws[br][0][d]; a1 += xv * sws[br][1][d];
            a2 += xv * sws[br][2][d]; a3 += xv * sws[br][3][d];
            p0 += xv * su [br][0][d]; p1 += xv * su [br][1][d];
            p2 += xv * su [br][2][d]; p3 += xv * su [br][3][d];
        }
        #pragma unroll
        for (int o = 16; o; o >>= 1) {
            a0 += __shfl_xor_sync(0xffffffffu, a0, o);
            a1 += __shfl_xor_sync(0xffffffffu, a1, o);
            a2 += __shfl_xor_sync(0xffffffffu, a2, o);
            a3 += __shfl_xor_sync(0xffffffffu, a3, o);
            p0 += __shfl_xor_sync(0xffffffffu, p0, o);
            p1 += __shfl_xor_sync(0xffffffffu, p1, o);
            p2 += __shfl_xor_sync(0xffffffffu, p2, o);
            p3 += __shfl_xor_sync(0xffffffffu, p3, o);
        }
        float ev[HH] = { a0 + adst0, a1 + adst1, a2 + adst2, a3 + adst3 };
        float pv[HH] = { p0, p1, p2, p3 };
        #pragma unroll
        for (int h = 0; h < HH; ++h) {
            float e = ev[h] > 0.f ? ev[h] : NEG_SLOPE * ev[h];
            float nm = fmaxf(m[h], e);
            float fo = __expf(m[h] - nm);
            float fn = __expf(e - nm);
            sA[h] = sA[h] * fo + fn;
            tA[h] = tA[h] * fo + pv[h] * fn;
            m[h]  = nm;
        }
    }

    if (lane == 0) {
        #pragma unroll
        for (int h = 0; h < HH; ++h) { wM[warp][h] = m[h]; wS[warp][h] = sA[h]; wT[warp][h] = tA[h]; }
    }
    __syncthreads();

    // Parallel deterministic merge: warp 0 lanes 0..7, one (branch, head) each
    if (warp == 0) {
        float val = 0.f;
        if (lane < 8) {
            const int brx = lane >> 2, h = lane & 3;
            float M = NEGINF, S = 0.f, T = 0.f;
            #pragma unroll
            for (int w = 4 * brx; w < 4 * brx + 4; ++w) {
                float mw_ = wM[w][h], sw_ = wS[w][h], tw_ = wT[w][h];
                if (sw_ != 0.f) {
                    float nm = fmaxf(M, mw_);
                    float fo = __expf(M - nm);
                    float fn = __expf(mw_ - nm);
                    S = S * fo + sw_ * fn;
                    T = T * fo + tw_ * fn;
                    M = nm;
                }
            }
            val = __fdividef(T, S) * (1.f / HH);
        }
        #pragma unroll
        for (int o = 4; o; o >>= 1) val += __shfl_xor_sync(0xffffffffu, val, o);
        if (lane == 0) out[b] = val + g_const;
    }
}

extern "C" void kernel_launch(void* const* d_in, const int* in_sizes, int n_in,
                              void* d_out, int out_size) {
    const int*   nbr1 = (const int*)  d_in[0];
    const int*   nbr2 = (const int*)  d_in[1];
    const int*   adj1 = (const int*)  d_in[2];
    const int*   adj2 = (const int*)  d_in[3];
    const float* emb  = (const float*)d_in[4];
    const float* W1   = (const float*)d_in[5];
    const float* as1  = (const float*)d_in[6];
    const float* ad1  = (const float*)d_in[7];
    const float* b1   = (const float*)d_in[8];
    const float* W2   = (const float*)d_in[9];
    const float* as2  = (const float*)d_in[10];
    const float* ad2  = (const float*)d_in[11];
    const float* b2   = (const float*)d_in[12];
    const float* mw   = (const float*)d_in[13];
    const float* mb   = (const float*)d_in[14];
    float* out = (float*)d_out;

    gat_fused<<<8 + BB, 256>>>(W1, as1, ad1, W2, as2, ad2, mw, mb, b1, b2,
                               adj1, adj2, nbr1, nbr2, emb, out);
}